// round 14
// baseline (speedup 1.0000x reference)
#include <cuda_runtime.h>
#include <cuda_fp16.h>
#include <cstdint>

#define Bb 4
#define Hh 16
#define Ss 1024
#define Dd 128
#define BM 128
#define BN 64
#define NT (Ss/BN)
#define TEMP 11.313708498984761f

// ---- kernel A smem (32-bit words) ----
#define OQ16 0                      // Q frag-major fp16 [mb8][kk8][lane32][4w] = 8192 w
#define OK16 8192                   // K fp16 row-major [64][68w] x2 bufs
#define KBUF 4352
#define A_SMEM_BYTES ((8192 + 2*4352)*4)   // 67584

// ---- kernel B smem ----
#define VBUF 4352                   // V fp16 kpair-packed [32][136w]
#define B_SMEM_BYTES (2*4352*4)     // 34816

__device__ unsigned char g_flags[Bb*8*16];

__device__ __forceinline__ uint32_t hpack(float lo, float hi){
    uint32_t r; asm("cvt.rn.f16x2.f32 %0, %1, %2;" : "=r"(r) : "f"(hi), "f"(lo)); return r;
}
__device__ __forceinline__ void mma16(float* c, uint32_t a0, uint32_t a1, uint32_t a2, uint32_t a3,
                                      uint32_t b0, uint32_t b1){
    asm volatile(
        "mma.sync.aligned.m16n8k16.row.col.f32.f16.f16.f32 "
        "{%0,%1,%2,%3},{%4,%5,%6,%7},{%8,%9},{%0,%1,%2,%3};"
        : "+f"(c[0]), "+f"(c[1]), "+f"(c[2]), "+f"(c[3])
        : "r"(a0), "r"(a1), "r"(a2), "r"(a3), "r"(b0), "r"(b1));
}

extern __shared__ uint32_t sm[];

// ---- pre-pass: per (b, qtile128, ktile64) all-ones mask flag ----
__global__ void mask_flags_kernel(const int* __restrict__ mask){
    const int kt = blockIdx.x, qt = blockIdx.y, b = blockIdx.z;
    const int* mb = mask + ((size_t)b*Ss + (size_t)qt*BM)*Ss + kt*BN;
    int ok = 1;
    #pragma unroll
    for (int i = 0; i < 8; i++) {
        int idx = threadIdx.x + i*256;
        int r = idx >> 4, c = (idx & 15) * 4;
        int4 m = *(const int4*)(mb + (size_t)r*Ss + c);
        ok &= (m.x && m.y && m.z && m.w) ? 1 : 0;
    }
    ok = __syncthreads_and(ok);
    if (threadIdx.x == 0) g_flags[(b*8 + qt)*16 + kt] = (unsigned char)ok;
}

// ====================== KERNEL A: S = clip(mask(QK^T/T)) -> attn (f32) ======================
__global__ __launch_bounds__(256, 2)
void sdpa_qk(const float* __restrict__ q, const float* __restrict__ k,
             const int* __restrict__ mask, float* __restrict__ attn)
{
    const int tid  = threadIdx.x;
    const int lane = tid & 31;
    const int g    = lane >> 2, tg = lane & 3;
    const int w    = tid >> 5;
    const int wm   = w & 3, wn = w >> 2;        // 4(m) x 2(n)
    const int bh   = blockIdx.y;
    const int q0   = blockIdx.x * BM;
    const int b    = bh >> 4;
    const size_t mbase = (size_t)b * Ss * Ss;
    const unsigned char* flags = &g_flags[(b*8 + blockIdx.x)*16];

    const float* kb = k + (size_t)bh*Ss*Dd;
    float* ag_base = attn + (size_t)bh*Ss*Ss + (size_t)q0*Ss;

    // Q -> frag-major fp16 (scaled), all 256 threads
    {
        const float invT = 1.0f / TEMP;
        const float4* qg = (const float4*)(q + ((size_t)bh*Ss + q0)*Dd);
        #pragma unroll
        for (int i = 0; i < 16; i++) {
            int idx = tid + i*256;             // [128 r][32 c4]
            int r = idx >> 5, c4 = idx & 31;
            float4 t = qg[idx];
            uint32_t p0 = hpack(t.x*invT, t.y*invT);
            uint32_t p1 = hpack(t.z*invT, t.w*invT);
            int mb_ = r >> 4, kk = c4 >> 2;
            int khalf = (c4 & 3) >= 2;
            int tg0 = 2*(c4 & 1);
            int j = ((r >> 3) & 1) + 2*khalf;
            uint32_t wbase = (uint32_t)(((mb_*8 + kk)*32 + (r&7)*4 + tg0)*4 + j);
            sm[OQ16 + wbase]     = p0;
            sm[OQ16 + wbase + 4] = p1;
        }
    }
    // K(0) -> buf0
    {
        const float4* kp4 = (const float4*)kb;
        #pragma unroll
        for (int i = 0; i < 8; i++) {
            int idx = tid + i*256;             // [64 r][32 c4]
            int r = idx >> 5, c4 = idx & 31;
            float4 t = kp4[idx];
            *(uint2*)&sm[OK16 + r*68 + c4*2] =
                make_uint2(hpack(t.x, t.y), hpack(t.z, t.w));
        }
    }
    __syncthreads();

    for (int nt = 0; nt < NT; nt++) {
        float4 kf[8];
        if (nt < NT-1) {
            const float4* kp4 = (const float4*)(kb + (size_t)(nt+1)*BN*Dd);
            #pragma unroll
            for (int i = 0; i < 8; i++) kf[i] = kp4[tid + i*256];
        }
        // GEMM1 on buf nt&1
        const uint32_t* sk = sm + OK16 + (nt & 1)*KBUF;
        float sacc[2][4][4];
        #pragma unroll
        for (int mi = 0; mi < 2; mi++)
            #pragma unroll
            for (int ni = 0; ni < 4; ni++)
                { sacc[mi][ni][0]=0.f; sacc[mi][ni][1]=0.f; sacc[mi][ni][2]=0.f; sacc[mi][ni][3]=0.f; }
        #pragma unroll
        for (int kk = 0; kk < 8; kk++) {
            uint4 aa0 = *(const uint4*)&sm[OQ16 + ((2*wm  )*8 + kk)*128 + lane*4];
            uint4 aa1 = *(const uint4*)&sm[OQ16 + ((2*wm+1)*8 + kk)*128 + lane*4];
            #pragma unroll
            for (int ni = 0; ni < 4; ni++) {
                int n = wn*32 + ni*8 + g;
                uint32_t b0 = sk[n*68 + kk*8 + tg];
                uint32_t b1 = sk[n*68 + kk*8 + tg + 4];
                mma16(sacc[0][ni], aa0.x, aa0.y, aa0.z, aa0.w, b0, b1);
                mma16(sacc[1][ni], aa1.x, aa1.y, aa1.z, aa1.w, b0, b1);
            }
        }
        // epilogue: mask + clip -> attn f32 directly (8-row x 32B full sectors)
        const int n0 = nt * BN;
        const unsigned char fl = flags[nt];
        #pragma unroll
        for (int mi = 0; mi < 2; mi++) {
            const int r = wm*32 + mi*16 + g;
            #pragma unroll
            for (int ni = 0; ni < 4; ni++) {
                const int cc = wn*32 + ni*8 + 2*tg;
                float* s4 = sacc[mi][ni];
                float v0 = s4[0], v1 = s4[1], v2 = s4[2], v3 = s4[3];
                if (!fl) {
                    const int* mrow = mask + mbase + (size_t)(q0+r)*Ss + n0 + cc;
                    int2 m0 = *(const int2*)mrow;
                    int2 m1 = *(const int2*)(mrow + 8*Ss);
                    if (!m0.x) v0 = 0.f; if (!m0.y) v1 = 0.f;
                    if (!m1.x) v2 = 0.f; if (!m1.y) v3 = 0.f;
                }
                v0 = fminf(fmaxf(v0,0.f),15.f); v1 = fminf(fmaxf(v1,0.f),15.f);
                v2 = fminf(fmaxf(v2,0.f),15.f); v3 = fminf(fmaxf(v3,0.f),15.f);
                float* ar = ag_base + (size_t)r*Ss + n0 + cc;
                *(float2*)ar          = make_float2(v0, v1);
                *(float2*)(ar + 8*Ss) = make_float2(v2, v3);
            }
        }
        // publish K(nt+1)
        if (nt < NT-1) {
            uint32_t* skn = sm + OK16 + ((nt+1) & 1)*KBUF;
            #pragma unroll
            for (int i = 0; i < 8; i++) {
                int idx = tid + i*256;
                int r = idx >> 5, c4 = idx & 31;
                *(uint2*)&skn[r*68 + c4*2] =
                    make_uint2(hpack(kf[i].x, kf[i].y), hpack(kf[i].z, kf[i].w));
            }
        }
        __syncthreads();
    }
}

// ====================== KERNEL B: out = attn @ V ======================
__global__ __launch_bounds__(256)
void sdpa_sv(const float* __restrict__ v, const float* __restrict__ attn,
             float* __restrict__ out)
{
    const int tid  = threadIdx.x;
    const int lane = tid & 31;
    const int g    = lane >> 2, tg = lane & 3;
    const int w    = tid >> 5;
    const int wm   = w & 3, wn = w >> 2;        // 4(m) x 2(n/d)
    const int bh   = blockIdx.y;
    const int q0   = blockIdx.x * BM;

    const float* ab = attn + (size_t)bh*Ss*Ss + (size_t)q0*Ss;
    const float* vb = v + (size_t)bh*Ss*Dd;

    // A-fragment direct-LDG: thread loads f32 pairs for its own mma fragments.
    // pair p: row += (p&1)*8, col += (p>>1)*8
    float2 af[2][4][4];    // [mi][kkv][pair]
    float4 vf[8];
    uint32_t ah[2][4][4];

    auto aload = [&](int nt, float2 a[2][4][4]){
        const float* base = ab + nt*BN;
        #pragma unroll
        for (int mi = 0; mi < 2; mi++) {
            const int R = wm*32 + mi*16 + g;
            #pragma unroll
            for (int kkv = 0; kkv < 4; kkv++) {
                const float* rp = base + (size_t)R*Ss + kkv*16 + 2*tg;
                a[mi][kkv][0] = *(const float2*)(rp);
                a[mi][kkv][1] = *(const float2*)(rp + 8*Ss);
                a[mi][kkv][2] = *(const float2*)(rp + 8);
                a[mi][kkv][3] = *(const float2*)(rp + 8*Ss + 8);
            }
        }
    };
    auto apack = [&](float2 a[2][4][4]){
        #pragma unroll
        for (int mi = 0; mi < 2; mi++)
            #pragma unroll
            for (int kkv = 0; kkv < 4; kkv++)
                #pragma unroll
                for (int p = 0; p < 4; p++)
                    ah[mi][kkv][p] = hpack(a[mi][kkv][p].x, a[mi][kkv][p].y);
    };
    auto vload = [&](int nt, float4 f[8]){
        const float4* vp4 = (const float4*)(vb + (size_t)nt*BN*Dd);
        #pragma unroll
        for (int i = 0; i < 4; i++) {
            int idx = tid + i*256;             // [32 kp][32 c4]
            int kpi = idx >> 5, c4 = idx & 31;
            f[i]   = vp4[(2*kpi  )*32 + c4];
            f[4+i] = vp4[(2*kpi+1)*32 + c4];
        }
    };
    auto vsts = [&](int buf, float4 f[8]){
        uint32_t* sv = sm + buf*VBUF;
        #pragma unroll
        for (int i = 0; i < 4; i++) {
            int idx = tid + i*256;
            int kpi = idx >> 5, c4 = idx & 31;
            *(uint4*)&sv[kpi*136 + c4*4] = make_uint4(
                hpack(f[i].x, f[4+i].x), hpack(f[i].y, f[4+i].y),
                hpack(f[i].z, f[4+i].z), hpack(f[i].w, f[4+i].w));
        }
    };

    // prologue: tile 0
    aload(0, af); vload(0, vf);
    apack(af); vsts(0, vf);
    __syncthreads();

    float o[2][8][4];
    #pragma unroll
    for (int mi = 0; mi < 2; mi++)
        #pragma unroll
        for (int di = 0; di < 8; di++)
            { o[mi][di][0]=0.f; o[mi][di][1]=0.f; o[mi][di][2]=0.f; o[mi][di][3]=0.f; }

    for (int nt = 0; nt < NT; nt++) {
        float2 afn[2][4][4]; float4 vfn[8];
        if (nt < NT-1) { aload(nt+1, afn); vload(nt+1, vfn); }
        // GEMM2 on ah + V buf nt&1
        const uint32_t* sv = sm + (nt & 1)*VBUF;
        #pragma unroll
        for (int kkv = 0; kkv < 4; kkv++) {
            #pragma unroll
            for (int di = 0; di < 8; di++) {
                int n = wn*64 + di*8 + g;
                uint32_t b0 = sv[(kkv*8 + tg    )*136 + n];
                uint32_t b1 = sv[(kkv*8 + tg + 4)*136 + n];
                mma16(o[0][di], ah[0][kkv][0], ah[0][kkv][1], ah[0][kkv][2], ah[0][kkv][3], b0, b1);
                mma16(o[1][di], ah[1][kkv][0], ah[1][kkv][1], ah[1][kkv][2], ah[1][kkv][3], b0, b1);
            }
        }
        if (nt < NT-1) { vsts((nt+1) & 1, vfn); apack(afn); }
        __syncthreads();
    }

    // O writeout: direct STG.64 (full 32B sectors)
    float* og = out + ((size_t)bh*Ss + q0) * Dd;
    #pragma unroll
    for (int mi = 0; mi < 2; mi++) {
        const int r = wm*32 + mi*16 + g;
        #pragma unroll
        for (int di = 0; di < 8; di++) {
            const int c = wn*64 + di*8 + 2*tg;
            float* orow = og + (size_t)r*Dd + c;
            *(float2*)orow          = make_float2(o[mi][di][0], o[mi][di][1]);
            *(float2*)(orow + 8*Dd) = make_float2(o[mi][di][2], o[mi][di][3]);
        }
    }
}

extern "C" void kernel_launch(void* const* d_in, const int* in_sizes, int n_in,
                              void* d_out, int out_size)
{
    const float* q    = (const float*)d_in[0];
    const float* k    = (const float*)d_in[1];
    const float* v    = (const float*)d_in[2];
    const int*   mask = (const int*)  d_in[3];
    float* out  = (float*)d_out;
    float* attn = out + (size_t)Bb*Hh*Ss*Dd;   // tuple order: (out, attn)

    mask_flags_kernel<<<dim3(16, 8, Bb), 256>>>(mask);

    cudaFuncSetAttribute(sdpa_qk,
                         cudaFuncAttributeMaxDynamicSharedMemorySize, A_SMEM_BYTES);
    cudaFuncSetAttribute(sdpa_sv,
                         cudaFuncAttributeMaxDynamicSharedMemorySize, B_SMEM_BYTES);

    dim3 grid(Ss/BM, Bb*Hh);
    sdpa_qk<<<grid, 256, A_SMEM_BYTES>>>(q, k, mask, attn);
    sdpa_sv<<<grid, 256, B_SMEM_BYTES>>>(v, attn, out);
}

// round 15
// speedup vs baseline: 1.3913x; 1.3913x over previous
#include <cuda_runtime.h>
#include <cuda_fp16.h>
#include <cstdint>

#define Bb 4
#define Hh 16
#define Ss 1024
#define Dd 128
#define BM 128
#define BN 64
#define NT (Ss/BN)
#define THREADS 512
#define TEMP 11.313708498984761f

// ---- smem word offsets (32-bit words) ----
#define OK16 0                      // K fp16 row-major [64][68w] x2 bufs
#define KBUF 4352
#define OV16 8704                   // V fp16 kpair-packed [32][136w] x2 bufs
#define VBUF 4352
#define OS16 17408                  // S fp16 frag-major [mb8][kkv4][lane32][4w] x2 bufs
#define SBUF 4096
#define SMEM_WORDS 25600
#define SMEM_BYTES (SMEM_WORDS*4)   // 102400

__device__ unsigned char g_flags[Bb*8*16];

__device__ __forceinline__ uint32_t hpack(float lo, float hi){
    uint32_t r; asm("cvt.rn.f16x2.f32 %0, %1, %2;" : "=r"(r) : "f"(hi), "f"(lo)); return r;
}
__device__ __forceinline__ void mma16(float* c, uint32_t a0, uint32_t a1, uint32_t a2, uint32_t a3,
                                      uint32_t b0, uint32_t b1){
    asm volatile(
        "mma.sync.aligned.m16n8k16.row.col.f32.f16.f16.f32 "
        "{%0,%1,%2,%3},{%4,%5,%6,%7},{%8,%9},{%0,%1,%2,%3};"
        : "+f"(c[0]), "+f"(c[1]), "+f"(c[2]), "+f"(c[3])
        : "r"(a0), "r"(a1), "r"(a2), "r"(a3), "r"(b0), "r"(b1));
}

extern __shared__ uint32_t sm[];

// ---- pre-pass: per (b, qtile128, ktile64) all-ones mask flag ----
__global__ void mask_flags_kernel(const int* __restrict__ mask){
    const int kt = blockIdx.x, qt = blockIdx.y, b = blockIdx.z;
    const int* mb = mask + ((size_t)b*Ss + (size_t)qt*BM)*Ss + kt*BN;
    int ok = 1;
    #pragma unroll
    for (int i = 0; i < 8; i++) {
        int idx = threadIdx.x + i*256;
        int r = idx >> 4, c = (idx & 15) * 4;
        int4 m = *(const int4*)(mb + (size_t)r*Ss + c);
        ok &= (m.x && m.y && m.z && m.w) ? 1 : 0;
    }
    ok = __syncthreads_and(ok);
    if (threadIdx.x == 0) g_flags[(b*8 + qt)*16 + kt] = (unsigned char)ok;
}

__global__ __launch_bounds__(THREADS, 1)
void sdpa_relu15_pp(const float* __restrict__ q, const float* __restrict__ k,
                    const float* __restrict__ v, const int* __restrict__ mask,
                    float* __restrict__ out, float* __restrict__ attn)
{
    const int tid  = threadIdx.x;
    const int lane = tid & 31;
    const int g    = lane >> 2, tg = lane & 3;
    const int bh   = blockIdx.y;
    const int q0   = blockIdx.x * BM;
    const int b    = bh >> 4;
    const size_t mbase = (size_t)b * Ss * Ss;
    const unsigned char* flags = &g_flags[(b*8 + blockIdx.x)*16];

    const float* kb = k + (size_t)bh*Ss*Dd;
    const float* vb = v + (size_t)bh*Ss*Dd;
    float* ag_base = attn + (size_t)bh*Ss*Ss + (size_t)q0*Ss;

    if (tid < 256) {
        // ================= warpgroup A: GEMM1 owner, Q resident in regs =================
        const int w  = tid >> 5;
        const int wm = w & 3, wn = (w >> 2) & 1;    // 4(m) x 2(n)

        // Q fragments -> registers (scaled fp16). qh[mb][kk][0..3]
        uint32_t qh[2][8][4];
        {
            const float invT = 1.0f / TEMP;
            #pragma unroll
            for (int mb_ = 0; mb_ < 2; mb_++) {
                const int R = wm*32 + mb_*16 + g;
                const float* r0p = q + ((size_t)bh*Ss + q0 + R)*Dd;
                const float* r1p = r0p + 8*Dd;
                #pragma unroll
                for (int kk = 0; kk < 8; kk++) {
                    const int c = kk*16 + 2*tg;
                    float2 x0 = *(const float2*)(r0p + c);
                    float2 x1 = *(const float2*)(r1p + c);
                    float2 x2 = *(const float2*)(r0p + c + 8);
                    float2 x3 = *(const float2*)(r1p + c + 8);
                    qh[mb_][kk][0] = hpack(x0.x*invT, x0.y*invT);
                    qh[mb_][kk][1] = hpack(x1.x*invT, x1.y*invT);
                    qh[mb_][kk][2] = hpack(x2.x*invT, x2.y*invT);
                    qh[mb_][kk][3] = hpack(x3.x*invT, x3.y*invT);
                }
            }
        }

        auto gemm1_epi = [&](int t){
            const uint32_t* sk = sm + OK16 + (t & 1)*KBUF;
            float sacc[2][4][4];
            #pragma unroll
            for (int mi = 0; mi < 2; mi++)
                #pragma unroll
                for (int ni = 0; ni < 4; ni++)
                    { sacc[mi][ni][0]=0.f; sacc[mi][ni][1]=0.f; sacc[mi][ni][2]=0.f; sacc[mi][ni][3]=0.f; }
            #pragma unroll
            for (int kk = 0; kk < 8; kk++) {
                #pragma unroll
                for (int ni = 0; ni < 4; ni++) {
                    int n = wn*32 + ni*8 + g;
                    uint32_t b0 = sk[n*68 + kk*8 + tg];
                    uint32_t b1 = sk[n*68 + kk*8 + tg + 4];
                    mma16(sacc[0][ni], qh[0][kk][0], qh[0][kk][1], qh[0][kk][2], qh[0][kk][3], b0, b1);
                    mma16(sacc[1][ni], qh[1][kk][0], qh[1][kk][1], qh[1][kk][2], qh[1][kk][3], b0, b1);
                }
            }
            // epilogue: mask+clip -> attn f32 STG (direct) + S16 frag STS
            const int n0 = t * BN;
            const unsigned char fl = flags[t];
            uint32_t* s16 = sm + OS16 + (t & 1)*SBUF;
            #pragma unroll
            for (int mi = 0; mi < 2; mi++) {
                const int r = wm*32 + mi*16 + g;
                const int mb_w = wm*2 + mi;
                #pragma unroll
                for (int ni = 0; ni < 4; ni++) {
                    const int cc = wn*32 + ni*8 + 2*tg;
                    float* s4 = sacc[mi][ni];
                    float v0 = s4[0], v1 = s4[1], v2 = s4[2], v3 = s4[3];
                    if (!fl) {
                        const int* mrow = mask + mbase + (size_t)(q0+r)*Ss + n0 + cc;
                        int2 m0 = *(const int2*)mrow;
                        int2 m1 = *(const int2*)(mrow + 8*Ss);
                        if (!m0.x) v0 = 0.f; if (!m0.y) v1 = 0.f;
                        if (!m1.x) v2 = 0.f; if (!m1.y) v3 = 0.f;
                    }
                    v0 = fminf(fmaxf(v0,0.f),15.f); v1 = fminf(fmaxf(v1,0.f),15.f);
                    v2 = fminf(fmaxf(v2,0.f),15.f); v3 = fminf(fmaxf(v3,0.f),15.f);
                    float* ar = ag_base + (size_t)r*Ss + n0 + cc;
                    *(float2*)ar          = make_float2(v0, v1);
                    *(float2*)(ar + 8*Ss) = make_float2(v2, v3);
                    const int kkv = wn*2 + (ni >> 1);
                    uint32_t wadr = (uint32_t)(((mb_w*4 + kkv)*32 + g*4 + tg)*4 + (ni&1)*2);
                    *(uint2*)&s16[wadr] = make_uint2(hpack(v0, v1), hpack(v2, v3));
                }
            }
        };

        __syncthreads();                 // (1) K(0) ready
        gemm1_epi(0);
        __syncthreads();                 // (2) S16(0) ready; K(1)/V(0) ready
        for (int nt = 0; nt < NT; nt++) {
            if (nt < NT-1) gemm1_epi(nt+1);
            __syncthreads();             // phase barrier
        }
    } else {
        // ================= warpgroup B: GEMM2 owner + K/V producer =================
        const int w2 = (tid >> 5) - 8;
        const int wm = w2 & 3, wn = (w2 >> 2) & 1;  // 4(m) x 2(d)
        const int pt = tid - 256;                   // 0..255

        auto kldg = [&](int t, float4 st[8]){
            const float4* kp4 = (const float4*)(kb + (size_t)t*BN*Dd);
            #pragma unroll
            for (int i = 0; i < 8; i++) st[i] = kp4[pt + i*256];
        };
        auto ksts = [&](int buf, float4 st[8]){
            uint32_t* sk = sm + OK16 + buf*KBUF;
            #pragma unroll
            for (int i = 0; i < 8; i++) {
                int idx = pt + i*256;              // [64 r][32 c4]
                int r = idx >> 5, c4 = idx & 31;
                *(uint2*)&sk[r*68 + c4*2] =
                    make_uint2(hpack(st[i].x, st[i].y), hpack(st[i].z, st[i].w));
            }
        };
        auto vldg = [&](int t, float4 st[8]){
            const float4* vp4 = (const float4*)(vb + (size_t)t*BN*Dd);
            #pragma unroll
            for (int i = 0; i < 4; i++) {
                int idx = pt + i*256;              // [32 kp][32 c4]
                int kpi = idx >> 5, c4 = idx & 31;
                st[i]   = vp4[(2*kpi  )*32 + c4];
                st[4+i] = vp4[(2*kpi+1)*32 + c4];
            }
        };
        auto vsts = [&](int buf, float4 st[8]){
            uint32_t* sv = sm + OV16 + buf*VBUF;
            #pragma unroll
            for (int i = 0; i < 4; i++) {
                int idx = pt + i*256;
                int kpi = idx >> 5, c4 = idx & 31;
                *(uint4*)&sv[kpi*136 + c4*4] = make_uint4(
                    hpack(st[i].x, st[4+i].x), hpack(st[i].y, st[4+i].y),
                    hpack(st[i].z, st[4+i].z), hpack(st[i].w, st[4+i].w));
            }
        };

        // prologue: K(0); then K(1) + V(0)
        {
            float4 st[8];
            kldg(0, st); ksts(0, st);
            __syncthreads();             // (1)
            kldg(1, st); ksts(1, st);
            vldg(0, st); vsts(0, st);
            __syncthreads();             // (2)
        }

        float o[2][8][4];
        #pragma unroll
        for (int mi = 0; mi < 2; mi++)
            #pragma unroll
            for (int di = 0; di < 8; di++)
                { o[mi][di][0]=0.f; o[mi][di][1]=0.f; o[mi][di][2]=0.f; o[mi][di][3]=0.f; }

        auto gemm2_half = [&](int t, int kv0){
            const uint32_t* sv  = sm + OV16 + (t & 1)*VBUF;
            const uint32_t* s16 = sm + OS16 + (t & 1)*SBUF;
            #pragma unroll
            for (int kkv = kv0; kkv < kv0 + 2; kkv++) {
                uint4 a0v = *(const uint4*)&s16[((wm*2  )*4 + kkv)*128 + lane*4];
                uint4 a1v = *(const uint4*)&s16[((wm*2+1)*4 + kkv)*128 + lane*4];
                #pragma unroll
                for (int di = 0; di < 8; di++) {
                    int n = wn*64 + di*8 + g;
                    uint32_t b0 = sv[(kkv*8 + tg    )*136 + n];
                    uint32_t b1 = sv[(kkv*8 + tg + 4)*136 + n];
                    mma16(o[0][di], a0v.x, a0v.y, a0v.z, a0v.w, b0, b1);
                    mma16(o[1][di], a1v.x, a1v.y, a1v.z, a1v.w, b0, b1);
                }
            }
        };

        for (int nt = 0; nt < NT; nt++) {
            float4 st[8];
            const bool ldk = nt < NT-2, ldv = nt < NT-1;
            if (ldk) kldg(nt+2, st);
            gemm2_half(nt, 0);           // LDG latency hides under MMAs
            if (ldk) ksts((nt+2) & 1, st);
            if (ldv) vldg(nt+1, st);
            gemm2_half(nt, 2);
            if (ldv) vsts((nt+1) & 1, st);
            __syncthreads();             // phase barrier
        }

        // O writeout: direct STG.64 (full 32B sectors)
        float* og = out + ((size_t)bh*Ss + q0) * Dd;
        #pragma unroll
        for (int mi = 0; mi < 2; mi++) {
            const int r = wm*32 + mi*16 + g;
            #pragma unroll
            for (int di = 0; di < 8; di++) {
                const int c = wn*64 + di*8 + 2*tg;
                float* orow = og + (size_t)r*Dd + c;
                *(float2*)orow          = make_float2(o[mi][di][0], o[mi][di][1]);
                *(float2*)(orow + 8*Dd) = make_float2(o[mi][di][2], o[mi][di][3]);
            }
        }
    }
}

extern "C" void kernel_launch(void* const* d_in, const int* in_sizes, int n_in,
                              void* d_out, int out_size)
{
    const float* q    = (const float*)d_in[0];
    const float* k    = (const float*)d_in[1];
    const float* v    = (const float*)d_in[2];
    const int*   mask = (const int*)  d_in[3];
    float* out  = (float*)d_out;
    float* attn = out + (size_t)Bb*Hh*Ss*Dd;   // tuple order: (out, attn)

    mask_flags_kernel<<<dim3(16, 8, Bb), 256>>>(mask);

    cudaFuncSetAttribute(sdpa_relu15_pp,
                         cudaFuncAttributeMaxDynamicSharedMemorySize, SMEM_BYTES);
    dim3 grid(Ss/BM, Bb*Hh);
    sdpa_relu15_pp<<<grid, THREADS, SMEM_BYTES>>>(q, k, v, mask, out, attn);
}

// round 16
// speedup vs baseline: 1.5071x; 1.0833x over previous
#include <cuda_runtime.h>
#include <cuda_fp16.h>
#include <cstdint>

#define Bb 4
#define Hh 16
#define Ss 1024
#define Dd 128
#define BM 128
#define BN 64
#define NT (Ss/BN)
#define THREADS 512
#define TEMP 11.313708498984761f

// ---- smem word offsets (32-bit words) ----
#define OK16 0                      // K fp16 row-major [64][68w] x2 bufs
#define KBUF 4352
#define OV16 8704                   // V fp16 kpair-packed [32][136w] x2 bufs
#define VBUF 4352
#define OS16 17408                  // S fp16 frag-major [mb8][kkv4][lane32][4w] x2 bufs
#define SBUF 4096
#define SMEM_WORDS 25600
#define SMEM_BYTES (SMEM_WORDS*4)   // 102400

__device__ unsigned char g_flags[Bb*8*16];

__device__ __forceinline__ uint32_t hpack(float lo, float hi){
    uint32_t r; asm("cvt.rn.f16x2.f32 %0, %1, %2;" : "=r"(r) : "f"(hi), "f"(lo)); return r;
}
__device__ __forceinline__ void mma16(float* c, uint32_t a0, uint32_t a1, uint32_t a2, uint32_t a3,
                                      uint32_t b0, uint32_t b1){
    asm volatile(
        "mma.sync.aligned.m16n8k16.row.col.f32.f16.f16.f32 "
        "{%0,%1,%2,%3},{%4,%5,%6,%7},{%8,%9},{%0,%1,%2,%3};"
        : "+f"(c[0]), "+f"(c[1]), "+f"(c[2]), "+f"(c[3])
        : "r"(a0), "r"(a1), "r"(a2), "r"(a3), "r"(b0), "r"(b1));
}
__device__ __forceinline__ void ldsm_x4(uint32_t* r, uint32_t addr){
    asm volatile("ldmatrix.sync.aligned.m8n8.x4.shared.b16 {%0,%1,%2,%3}, [%4];"
        : "=r"(r[0]), "=r"(r[1]), "=r"(r[2]), "=r"(r[3]) : "r"(addr));
}
__device__ __forceinline__ uint32_t smem_u32(const void* p){
    uint32_t a; asm("{ .reg .u64 t; cvta.to.shared.u64 t, %1; cvt.u32.u64 %0, t; }" : "=r"(a) : "l"(p));
    return a;
}

extern __shared__ uint32_t sm[];

// ---- pre-pass: per (b, qtile128, ktile64) all-ones mask flag ----
__global__ void mask_flags_kernel(const int* __restrict__ mask){
    const int kt = blockIdx.x, qt = blockIdx.y, b = blockIdx.z;
    const int* mb = mask + ((size_t)b*Ss + (size_t)qt*BM)*Ss + kt*BN;
    int ok = 1;
    #pragma unroll
    for (int i = 0; i < 8; i++) {
        int idx = threadIdx.x + i*256;
        int r = idx >> 4, c = (idx & 15) * 4;
        int4 m = *(const int4*)(mb + (size_t)r*Ss + c);
        ok &= (m.x && m.y && m.z && m.w) ? 1 : 0;
    }
    ok = __syncthreads_and(ok);
    if (threadIdx.x == 0) g_flags[(b*8 + qt)*16 + kt] = (unsigned char)ok;
}

__global__ __launch_bounds__(THREADS, 1)
void sdpa_relu15_pp2(const float* __restrict__ q, const float* __restrict__ k,
                     const float* __restrict__ v, const int* __restrict__ mask,
                     float* __restrict__ out, float* __restrict__ attn)
{
    const int tid  = threadIdx.x;
    const int lane = tid & 31;
    const int g    = lane >> 2, tg = lane & 3;
    const int bh   = blockIdx.y;
    const int q0   = blockIdx.x * BM;
    const int b    = bh >> 4;
    const size_t mbase = (size_t)b * Ss * Ss;
    const unsigned char* flags = &g_flags[(b*8 + blockIdx.x)*16];
    const uint32_t smem_base = smem_u32(sm);

    const float* kb = k + (size_t)bh*Ss*Dd;
    const float* vb = v + (size_t)bh*Ss*Dd;
    float* ag_base = attn + (size_t)bh*Ss*Ss + (size_t)q0*Ss;

    if (tid < 256) {
        // ================= warpgroup A: GEMM1 owner, Q resident in regs =================
        const int w  = tid >> 5;
        const int wm = w & 3, wn = (w >> 2) & 1;    // 4(m) x 2(n)

        // Q fragments -> registers (scaled fp16). qh[mb][kk][0..3]
        uint32_t qh[2][8][4];
        {
            const float invT = 1.0f / TEMP;
            #pragma unroll
            for (int mb_ = 0; mb_ < 2; mb_++) {
                const int R = wm*32 + mb_*16 + g;
                const float* r0p = q + ((size_t)bh*Ss + q0 + R)*Dd;
                const float* r1p = r0p + 8*Dd;
                #pragma unroll
                for (int kk = 0; kk < 8; kk++) {
                    const int c = kk*16 + 2*tg;
                    float2 x0 = *(const float2*)(r0p + c);
                    float2 x1 = *(const float2*)(r1p + c);
                    float2 x2 = *(const float2*)(r0p + c + 8);
                    float2 x3 = *(const float2*)(r1p + c + 8);
                    qh[mb_][kk][0] = hpack(x0.x*invT, x0.y*invT);
                    qh[mb_][kk][1] = hpack(x1.x*invT, x1.y*invT);
                    qh[mb_][kk][2] = hpack(x2.x*invT, x2.y*invT);
                    qh[mb_][kk][3] = hpack(x3.x*invT, x3.y*invT);
                }
            }
        }

        // lane-specific ldmatrix base offsets (bytes within a K buffer)
        // call a (a=0 -> ni 0,1 ; a=1 -> ni 2,3): tiles (ni, k0),(ni, k8),(ni+1, k0),(ni+1, k8)
        const int tq = lane >> 3, rr = lane & 7;
        const int niq = tq >> 1, kh = tq & 1;
        const uint32_t offA0 = (uint32_t)(((wn*32 + (    niq)*8 + rr)*68 + kh*4) * 4);
        const uint32_t offA1 = (uint32_t)(((wn*32 + (2 + niq)*8 + rr)*68 + kh*4) * 4);

        auto gemm1_epi = [&](int t){
            const uint32_t skb = smem_base + (uint32_t)((OK16 + (t & 1)*KBUF)*4);
            const uint32_t a0b = skb + offA0, a1b = skb + offA1;
            float sacc[2][4][4];
            #pragma unroll
            for (int mi = 0; mi < 2; mi++)
                #pragma unroll
                for (int ni = 0; ni < 4; ni++)
                    { sacc[mi][ni][0]=0.f; sacc[mi][ni][1]=0.f; sacc[mi][ni][2]=0.f; sacc[mi][ni][3]=0.f; }

            // 2-stage ldmatrix pipeline over kk: bst[stage][8] = frags (ni0..3 x {b0,b1})
            uint32_t bst[2][8];
            ldsm_x4(&bst[0][0], a0b);          // kk=0
            ldsm_x4(&bst[0][4], a1b);
            #pragma unroll
            for (int kk = 0; kk < 8; kk++) {
                const int cur = kk & 1;
                if (kk < 7) {
                    ldsm_x4(&bst[cur^1][0], a0b + (kk+1)*32);
                    ldsm_x4(&bst[cur^1][4], a1b + (kk+1)*32);
                }
                // frag layout: bst[.][0]=b0(ni0) [1]=b1(ni0) [2]=b0(ni1) [3]=b1(ni1)
                //              bst[.][4]=b0(ni2) [5]=b1(ni2) [6]=b0(ni3) [7]=b1(ni3)
                #pragma unroll
                for (int ni = 0; ni < 4; ni++) {
                    uint32_t b0 = bst[cur][2*ni], b1 = bst[cur][2*ni+1];
                    mma16(sacc[0][ni], qh[0][kk][0], qh[0][kk][1], qh[0][kk][2], qh[0][kk][3], b0, b1);
                    mma16(sacc[1][ni], qh[1][kk][0], qh[1][kk][1], qh[1][kk][2], qh[1][kk][3], b0, b1);
                }
            }
            // epilogue: mask+clip -> attn f32 STG (direct) + S16 frag STS
            const int n0 = t * BN;
            const unsigned char fl = flags[t];
            uint32_t* s16 = sm + OS16 + (t & 1)*SBUF;
            #pragma unroll
            for (int mi = 0; mi < 2; mi++) {
                const int r = wm*32 + mi*16 + g;
                const int mb_w = wm*2 + mi;
                #pragma unroll
                for (int ni = 0; ni < 4; ni++) {
                    const int cc = wn*32 + ni*8 + 2*tg;
                    float* s4 = sacc[mi][ni];
                    float v0 = s4[0], v1 = s4[1], v2 = s4[2], v3 = s4[3];
                    if (!fl) {
                        const int* mrow = mask + mbase + (size_t)(q0+r)*Ss + n0 + cc;
                        int2 m0 = *(const int2*)mrow;
                        int2 m1 = *(const int2*)(mrow + 8*Ss);
                        if (!m0.x) v0 = 0.f; if (!m0.y) v1 = 0.f;
                        if (!m1.x) v2 = 0.f; if (!m1.y) v3 = 0.f;
                    }
                    v0 = fminf(fmaxf(v0,0.f),15.f); v1 = fminf(fmaxf(v1,0.f),15.f);
                    v2 = fminf(fmaxf(v2,0.f),15.f); v3 = fminf(fmaxf(v3,0.f),15.f);
                    float* ar = ag_base + (size_t)r*Ss + n0 + cc;
                    *(float2*)ar          = make_float2(v0, v1);
                    *(float2*)(ar + 8*Ss) = make_float2(v2, v3);
                    const int kkv = wn*2 + (ni >> 1);
                    uint32_t wadr = (uint32_t)(((mb_w*4 + kkv)*32 + g*4 + tg)*4 + (ni&1)*2);
                    *(uint2*)&s16[wadr] = make_uint2(hpack(v0, v1), hpack(v2, v3));
                }
            }
        };

        __syncthreads();                 // (1) K(0) ready
        gemm1_epi(0);
        __syncthreads();                 // (2) S16(0) ready; K(1)/V(0) ready
        for (int nt = 0; nt < NT; nt++) {
            if (nt < NT-1) gemm1_epi(nt+1);
            __syncthreads();             // phase barrier
        }
    } else {
        // ================= warpgroup B: GEMM2 owner + K/V producer =================
        const int w2 = (tid >> 5) - 8;
        const int wm = w2 & 3, wn = (w2 >> 2) & 1;  // 4(m) x 2(d)
        const int pt = tid - 256;                   // 0..255

        auto kldg = [&](int t, float4 st[8]){
            const float4* kp4 = (const float4*)(kb + (size_t)t*BN*Dd);
            #pragma unroll
            for (int i = 0; i < 8; i++) st[i] = kp4[pt + i*256];
        };
        auto ksts = [&](int buf, float4 st[8]){
            uint32_t* sk = sm + OK16 + buf*KBUF;
            #pragma unroll
            for (int i = 0; i < 8; i++) {
                int idx = pt + i*256;              // [64 r][32 c4]
                int r = idx >> 5, c4 = idx & 31;
                *(uint2*)&sk[r*68 + c4*2] =
                    make_uint2(hpack(st[i].x, st[i].y), hpack(st[i].z, st[i].w));
            }
        };
        auto vldg = [&](int t, float4 st[8]){
            const float4* vp4 = (const float4*)(vb + (size_t)t*BN*Dd);
            #pragma unroll
            for (int i = 0; i < 4; i++) {
                int idx = pt + i*256;              // [32 kp][32 c4]
                int kpi = idx >> 5, c4 = idx & 31;
                st[i]   = vp4[(2*kpi  )*32 + c4];
                st[4+i] = vp4[(2*kpi+1)*32 + c4];
            }
        };
        auto vsts = [&](int buf, float4 st[8]){
            uint32_t* sv = sm + OV16 + buf*VBUF;
            #pragma unroll
            for (int i = 0; i < 4; i++) {
                int idx = pt + i*256;
                int kpi = idx >> 5, c4 = idx & 31;
                *(uint4*)&sv[kpi*136 + c4*4] = make_uint4(
                    hpack(st[i].x, st[4+i].x), hpack(st[i].y, st[4+i].y),
                    hpack(st[i].z, st[4+i].z), hpack(st[i].w, st[4+i].w));
            }
        };

        // prologue: K(0); then K(1) + V(0)
        {
            float4 st[8];
            kldg(0, st); ksts(0, st);
            __syncthreads();             // (1)
            kldg(1, st); ksts(1, st);
            vldg(0, st); vsts(0, st);
            __syncthreads();             // (2)
        }

        float o[2][8][4];
        #pragma unroll
        for (int mi = 0; mi < 2; mi++)
            #pragma unroll
            for (int di = 0; di < 8; di++)
                { o[mi][di][0]=0.f; o[mi][di][1]=0.f; o[mi][di][2]=0.f; o[mi][di][3]=0.f; }

        auto gemm2_half = [&](int t, int kv0){
            const uint32_t* sv  = sm + OV16 + (t & 1)*VBUF;
            const uint32_t* s16 = sm + OS16 + (t & 1)*SBUF;
            #pragma unroll
            for (int kkv = kv0; kkv < kv0 + 2; kkv++) {
                uint4 a0v = *(const uint4*)&s16[((wm*2  )*4 + kkv)*128 + lane*4];
                uint4 a1v = *(const uint4*)&s16[((wm*2+1)*4 + kkv)*128 + lane*4];
                // batch all B words first, then burst MMAs (loads drain in order)
                uint32_t bb[16];
                #pragma unroll
                for (int di = 0; di < 8; di++) {
                    int n = wn*64 + di*8 + g;
                    bb[2*di]   = sv[(kkv*8 + tg    )*136 + n];
                    bb[2*di+1] = sv[(kkv*8 + tg + 4)*136 + n];
                }
                #pragma unroll
                for (int di = 0; di < 8; di++) {
                    mma16(o[0][di], a0v.x, a0v.y, a0v.z, a0v.w, bb[2*di], bb[2*di+1]);
                    mma16(o[1][di], a1v.x, a1v.y, a1v.z, a1v.w, bb[2*di], bb[2*di+1]);
                }
            }
        };

        for (int nt = 0; nt < NT; nt++) {
            float4 st[8];
            const bool ldk = nt < NT-2, ldv = nt < NT-1;
            if (ldk) kldg(nt+2, st);
            gemm2_half(nt, 0);           // LDG latency hides under MMAs
            if (ldk) ksts((nt+2) & 1, st);
            if (ldv) vldg(nt+1, st);
            gemm2_half(nt, 2);
            if (ldv) vsts((nt+1) & 1, st);
            __syncthreads();             // phase barrier
        }

        // O writeout: direct STG.64 (full 32B sectors)
        float* og = out + ((size_t)bh*Ss + q0) * Dd;
        #pragma unroll
        for (int mi = 0; mi < 2; mi++) {
            const int r = wm*32 + mi*16 + g;
            #pragma unroll
            for (int di = 0; di < 8; di++) {
                const int c = wn*64 + di*8 + 2*tg;
                float* orow = og + (size_t)r*Dd + c;
                *(float2*)orow          = make_float2(o[mi][di][0], o[mi][di][1]);
                *(float2*)(orow + 8*Dd) = make_float2(o[mi][di][2], o[mi][di][3]);
            }
        }
    }
}

extern "C" void kernel_launch(void* const* d_in, const int* in_sizes, int n_in,
                              void* d_out, int out_size)
{
    const float* q    = (const float*)d_in[0];
    const float* k    = (const float*)d_in[1];
    const float* v    = (const float*)d_in[2];
    const int*   mask = (const int*)  d_in[3];
    float* out  = (float*)d_out;
    float* attn = out + (size_t)Bb*Hh*Ss*Dd;   // tuple order: (out, attn)

    mask_flags_kernel<<<dim3(16, 8, Bb), 256>>>(mask);

    cudaFuncSetAttribute(sdpa_relu15_pp2,
                         cudaFuncAttributeMaxDynamicSharedMemorySize, SMEM_BYTES);
    dim3 grid(Ss/BM, Bb*Hh);
    sdpa_relu15_pp2<<<grid, THREADS, SMEM_BYTES>>>(q, k, v, mask, out, attn);
}